// round 17
// baseline (speedup 1.0000x reference)
#include <cuda_runtime.h>
#include <cuda_bf16.h>
#include <math.h>
#include <stdint.h>

// GaussianScorer sm_103a — 2 launches:
//  1) gs_convert: emb fp32 -> g_Ah bf16 + g_e2 (exact fp32); tail blocks also
//     produce g_Bh = bf16(means*inv_var), g_m2, g_logc (prep fused).
//  2) gs_mm: bf16 mma.sync GEMM; B fully SMEM-resident (128KB, loaded once),
//     A via pure cp.async 4-stage ring. NO fp32 ingest chain in the mainloop.
// out[m,l] = logc - 0.5*e2[m] - 0.5*m2[l] + cross[m,l]
// Shapes: M=16384, L=128, K=512.

#define GS_M 16384
#define GS_K 512
#define GS_L 128
#define BM   128
#define BKT  64
#define NITER (GS_K / BKT)   // 8
#define NSTG 4

#define A_STAGE 16384        // 128 rows * 128B (64 bf16)
#define B_BLK   16384        // 128 rows * 128B per 64-k block
#define MOFF_OFF 0           // 128 f32: logc - 0.5*m2[l]
#define A_OFF    1024
#define B_OFF    (A_OFF + NSTG * A_STAGE)     // 66560
#define SMEM_MM  (B_OFF + 8 * B_BLK)          // 197632

__device__ __nv_bfloat16 g_Ah[GS_M * GS_K];   // 16 MB
__device__ float g_e2[GS_M];
__device__ __nv_bfloat16 g_Bh[GS_L * GS_K];
__device__ float g_m2[GS_L];
__device__ float g_logc;

static __device__ __forceinline__ uint32_t smem_u32(const void* p) {
    uint32_t a;
    asm("{ .reg .u64 t; cvta.to.shared.u64 t, %1; cvt.u32.u64 %0, t; }" : "=r"(a) : "l"(p));
    return a;
}

#define CP_ASYNC16(dst, src) \
    asm volatile("cp.async.cg.shared.global [%0], [%1], 16;" :: "r"(dst), "l"(src) : "memory")
#define CP_COMMIT() asm volatile("cp.async.commit_group;" ::: "memory")
#define CP_WAIT2()  asm volatile("cp.async.wait_group 2;" ::: "memory")

#define LDSM_X4(r, addr)                                                        \
    asm volatile("ldmatrix.sync.aligned.m8n8.x4.shared.b16 {%0,%1,%2,%3}, [%4];" \
        : "=r"((r)[0]), "=r"((r)[1]), "=r"((r)[2]), "=r"((r)[3]) : "r"(addr))

#define MMA_BF16(d, a, b0, b1)                                                  \
    asm volatile("mma.sync.aligned.m16n8k16.row.col.f32.bf16.bf16.f32 "         \
        "{%0,%1,%2,%3}, {%4,%5,%6,%7}, {%8,%9}, {%0,%1,%2,%3};"                 \
        : "+f"((d)[0]), "+f"((d)[1]), "+f"((d)[2]), "+f"((d)[3])                \
        : "r"((a)[0]), "r"((a)[1]), "r"((a)[2]), "r"((a)[3]), "r"(b0), "r"(b1))

// 128B rows, 8 x 16B chunks, chunk ^= row&7  (proven in R7)
#define SWZ(row, chunk) ((uint32_t)((row) * 128 + (((chunk) ^ ((row) & 7)) << 4)))

// ---------------- kernel 1: convert + e2 (+ fused B-prep in tail blocks) ----------------
// grid = GS_M/8 + 16 = 2064 blocks, 256 threads (8 warps, one row per warp).
__global__ __launch_bounds__(256)
void gs_convert(const float* __restrict__ emb, const float* __restrict__ means,
                const float* __restrict__ var) {
    const int wrp = threadIdx.x >> 5;
    const int lane = threadIdx.x & 31;
    const int blk = blockIdx.x;

    // per-lane var slice (64B) — L2-resident after first wave
    const float* vp = var + lane * 16;
    float4 v0 = *(const float4*)(vp);
    float4 v1 = *(const float4*)(vp + 4);
    float4 v2 = *(const float4*)(vp + 8);
    float4 v3 = *(const float4*)(vp + 12);
    float4 i0 = make_float4(1.0f / v0.x, 1.0f / v0.y, 1.0f / v0.z, 1.0f / v0.w);
    float4 i1 = make_float4(1.0f / v1.x, 1.0f / v1.y, 1.0f / v1.z, 1.0f / v1.w);
    float4 i2 = make_float4(1.0f / v2.x, 1.0f / v2.y, 1.0f / v2.z, 1.0f / v2.w);
    float4 i3 = make_float4(1.0f / v3.x, 1.0f / v3.y, 1.0f / v3.z, 1.0f / v3.w);

    if (blk < GS_M / 8) {
        // ---- A role: one M-row per warp ----
        const int row = blk * 8 + wrp;
        const float* src = emb + (size_t)row * GS_K + lane * 16;
        float4 a0 = *(const float4*)(src);
        float4 a1 = *(const float4*)(src + 4);
        float4 a2 = *(const float4*)(src + 8);
        float4 a3 = *(const float4*)(src + 12);

        float e2 = 0.0f;
        e2 = fmaf(a0.x * a0.x, i0.x, e2); e2 = fmaf(a0.y * a0.y, i0.y, e2);
        e2 = fmaf(a0.z * a0.z, i0.z, e2); e2 = fmaf(a0.w * a0.w, i0.w, e2);
        e2 = fmaf(a1.x * a1.x, i1.x, e2); e2 = fmaf(a1.y * a1.y, i1.y, e2);
        e2 = fmaf(a1.z * a1.z, i1.z, e2); e2 = fmaf(a1.w * a1.w, i1.w, e2);
        e2 = fmaf(a2.x * a2.x, i2.x, e2); e2 = fmaf(a2.y * a2.y, i2.y, e2);
        e2 = fmaf(a2.z * a2.z, i2.z, e2); e2 = fmaf(a2.w * a2.w, i2.w, e2);
        e2 = fmaf(a3.x * a3.x, i3.x, e2); e2 = fmaf(a3.y * a3.y, i3.y, e2);
        e2 = fmaf(a3.z * a3.z, i3.z, e2); e2 = fmaf(a3.w * a3.w, i3.w, e2);

        __nv_bfloat162 c0 = __floats2bfloat162_rn(a0.x, a0.y);
        __nv_bfloat162 c1 = __floats2bfloat162_rn(a0.z, a0.w);
        __nv_bfloat162 c2 = __floats2bfloat162_rn(a1.x, a1.y);
        __nv_bfloat162 c3 = __floats2bfloat162_rn(a1.z, a1.w);
        __nv_bfloat162 c4 = __floats2bfloat162_rn(a2.x, a2.y);
        __nv_bfloat162 c5 = __floats2bfloat162_rn(a2.z, a2.w);
        __nv_bfloat162 c6 = __floats2bfloat162_rn(a3.x, a3.y);
        __nv_bfloat162 c7 = __floats2bfloat162_rn(a3.z, a3.w);

        __nv_bfloat16* dst = g_Ah + (size_t)row * GS_K + lane * 16;
        *(uint4*)(dst)     = make_uint4(*(uint32_t*)&c0, *(uint32_t*)&c1,
                                        *(uint32_t*)&c2, *(uint32_t*)&c3);
        *(uint4*)(dst + 8) = make_uint4(*(uint32_t*)&c4, *(uint32_t*)&c5,
                                        *(uint32_t*)&c6, *(uint32_t*)&c7);

        #pragma unroll
        for (int o = 16; o > 0; o >>= 1) e2 += __shfl_xor_sync(0xffffffffu, e2, o);
        if (lane == 0) g_e2[row] = e2;
    } else {
        // ---- B role: one L-row per warp (16 blocks x 8 warps = 128 rows) ----
        const int l = (blk - GS_M / 8) * 8 + wrp;
        const float* src = means + (size_t)l * GS_K + lane * 16;
        float4 m0_ = *(const float4*)(src);
        float4 m1_ = *(const float4*)(src + 4);
        float4 m2_ = *(const float4*)(src + 8);
        float4 m3_ = *(const float4*)(src + 12);

        float4 b0 = make_float4(m0_.x * i0.x, m0_.y * i0.y, m0_.z * i0.z, m0_.w * i0.w);
        float4 b1 = make_float4(m1_.x * i1.x, m1_.y * i1.y, m1_.z * i1.z, m1_.w * i1.w);
        float4 b2 = make_float4(m2_.x * i2.x, m2_.y * i2.y, m2_.z * i2.z, m2_.w * i2.w);
        float4 b3 = make_float4(m3_.x * i3.x, m3_.y * i3.y, m3_.z * i3.z, m3_.w * i3.w);

        float m2 = 0.0f;
        m2 = fmaf(m0_.x, b0.x, m2); m2 = fmaf(m0_.y, b0.y, m2);
        m2 = fmaf(m0_.z, b0.z, m2); m2 = fmaf(m0_.w, b0.w, m2);
        m2 = fmaf(m1_.x, b1.x, m2); m2 = fmaf(m1_.y, b1.y, m2);
        m2 = fmaf(m1_.z, b1.z, m2); m2 = fmaf(m1_.w, b1.w, m2);
        m2 = fmaf(m2_.x, b2.x, m2); m2 = fmaf(m2_.y, b2.y, m2);
        m2 = fmaf(m2_.z, b2.z, m2); m2 = fmaf(m2_.w, b2.w, m2);
        m2 = fmaf(m3_.x, b3.x, m2); m2 = fmaf(m3_.y, b3.y, m2);
        m2 = fmaf(m3_.z, b3.z, m2); m2 = fmaf(m3_.w, b3.w, m2);

        __nv_bfloat162 c0 = __floats2bfloat162_rn(b0.x, b0.y);
        __nv_bfloat162 c1 = __floats2bfloat162_rn(b0.z, b0.w);
        __nv_bfloat162 c2 = __floats2bfloat162_rn(b1.x, b1.y);
        __nv_bfloat162 c3 = __floats2bfloat162_rn(b1.z, b1.w);
        __nv_bfloat162 c4 = __floats2bfloat162_rn(b2.x, b2.y);
        __nv_bfloat162 c5 = __floats2bfloat162_rn(b2.z, b2.w);
        __nv_bfloat162 c6 = __floats2bfloat162_rn(b3.x, b3.y);
        __nv_bfloat162 c7 = __floats2bfloat162_rn(b3.z, b3.w);

        __nv_bfloat16* dst = g_Bh + (size_t)l * GS_K + lane * 16;
        *(uint4*)(dst)     = make_uint4(*(uint32_t*)&c0, *(uint32_t*)&c1,
                                        *(uint32_t*)&c2, *(uint32_t*)&c3);
        *(uint4*)(dst + 8) = make_uint4(*(uint32_t*)&c4, *(uint32_t*)&c5,
                                        *(uint32_t*)&c6, *(uint32_t*)&c7);

        #pragma unroll
        for (int o = 16; o > 0; o >>= 1) m2 += __shfl_xor_sync(0xffffffffu, m2, o);
        if (lane == 0) g_m2[l] = m2;

        // logc: first B block, warp 0
        if (blk == GS_M / 8 && wrp == 0) {
            float lg = __logf(v0.x) + __logf(v0.y) + __logf(v0.z) + __logf(v0.w)
                     + __logf(v1.x) + __logf(v1.y) + __logf(v1.z) + __logf(v1.w)
                     + __logf(v2.x) + __logf(v2.y) + __logf(v2.z) + __logf(v2.w)
                     + __logf(v3.x) + __logf(v3.y) + __logf(v3.z) + __logf(v3.w);
            #pragma unroll
            for (int o = 16; o > 0; o >>= 1) lg += __shfl_xor_sync(0xffffffffu, lg, o);
            if (lane == 0) {
                const float FACTOR = -256.0f * 1.8378770664093453f;  // -E/2*ln(2pi)
                g_logc = FACTOR - 0.5f * lg;
            }
        }
    }
}

// ---------------- kernel 2: lean GEMM (B resident, A cp.async ring) ----------------
__global__ __launch_bounds__(512, 1)
void gs_mm(float* __restrict__ out) {
    extern __shared__ __align__(1024) char smem[];
    const uint32_t sb = smem_u32(smem);
    const int tid = threadIdx.x;
    const int m0 = blockIdx.x * BM;

    const int r = tid >> 2;           // 0..127
    const int q = tid & 3;            // 0..3 : chunks 2q, 2q+1
    const uint32_t d0 = SWZ(r, 2 * q);
    const uint32_t d1 = SWZ(r, 2 * q + 1);

    // ---- group 0: B resident (all 8 k-blocks) + A stage 0 ----
    const char* bsrc = (const char*)(g_Bh + (size_t)r * GS_K);
    #pragma unroll
    for (int kb = 0; kb < 8; kb++) {
        CP_ASYNC16(sb + B_OFF + kb * B_BLK + d0, bsrc + (kb * 64 + q * 16) * 2);
        CP_ASYNC16(sb + B_OFF + kb * B_BLK + d1, bsrc + (kb * 64 + q * 16 + 8) * 2);
    }
    const char* asrc = (const char*)(g_Ah + (size_t)(m0 + r) * GS_K);
    CP_ASYNC16(sb + A_OFF + d0, asrc + (q * 16) * 2);
    CP_ASYNC16(sb + A_OFF + d1, asrc + (q * 16 + 8) * 2);
    CP_COMMIT();
    // ---- groups 1,2: A stages 1,2 ----
    #pragma unroll
    for (int s = 1; s < 3; s++) {
        CP_ASYNC16(sb + A_OFF + s * A_STAGE + d0, asrc + (s * BKT + q * 16) * 2);
        CP_ASYNC16(sb + A_OFF + s * A_STAGE + d1, asrc + (s * BKT + q * 16 + 8) * 2);
        CP_COMMIT();
    }

    if (tid < 128)
        ((float*)(smem + MOFF_OFF))[tid] = g_logc - 0.5f * g_m2[tid];

    const int lane = tid & 31;
    const int g = lane >> 2;
    const int tig = lane & 3;
    const int wid = tid >> 5;         // 0..15
    const int wm = wid >> 2;          // 0..3 -> 32 rows
    const int wn = wid & 3;           // 0..3 -> 32 cols
    const int mm = lane >> 3;
    const int mrow = lane & 7;
    const int rowA0 = wm * 32 + (mm & 1) * 8 + mrow;
    const int rowB0 = wn * 32 + (mm >> 1) * 8 + mrow;
    const int cA = mm >> 1;
    const int cB = mm & 1;

    float acc[2][4][4];
    #pragma unroll
    for (int mt = 0; mt < 2; mt++)
        #pragma unroll
        for (int nt = 0; nt < 4; nt++)
            #pragma unroll
            for (int j = 0; j < 4; j++) acc[mt][nt][j] = 0.0f;

    #pragma unroll
    for (int it = 0; it < NITER; ++it) {
        CP_WAIT2();
        __syncthreads();              // stage it (B+A0 on it=0) visible; prior reads done

        if (it + 3 < NITER) {
            const int s = (it + 3) & (NSTG - 1);
            CP_ASYNC16(sb + A_OFF + s * A_STAGE + d0, asrc + ((it + 3) * BKT + q * 16) * 2);
            CP_ASYNC16(sb + A_OFF + s * A_STAGE + d1, asrc + ((it + 3) * BKT + q * 16 + 8) * 2);
            CP_COMMIT();
        } else {
            CP_COMMIT();              // keep wait_group arithmetic valid
        }

        const uint32_t As = sb + A_OFF + (it & (NSTG - 1)) * A_STAGE;
        const uint32_t Bs = sb + B_OFF + it * B_BLK;

        #pragma unroll
        for (int ks = 0; ks < 4; ks++) {
            const int c0 = ks * 2;
            uint32_t af[2][4], bq[2][4];
            LDSM_X4(af[0], As + SWZ(rowA0,      c0 + cA));
            LDSM_X4(af[1], As + SWZ(rowA0 + 16, c0 + cA));
            LDSM_X4(bq[0], Bs + SWZ(rowB0,      c0 + cB));
            LDSM_X4(bq[1], Bs + SWZ(rowB0 + 16, c0 + cB));
            #pragma unroll
            for (int mt = 0; mt < 2; mt++) {
                MMA_BF16(acc[mt][0], af[mt], bq[0][0], bq[0][1]);
                MMA_BF16(acc[mt][1], af[mt], bq[0][2], bq[0][3]);
                MMA_BF16(acc[mt][2], af[mt], bq[1][0], bq[1][1]);
                MMA_BF16(acc[mt][3], af[mt], bq[1][2], bq[1][3]);
            }
        }
    }

    const float* moff = (const float*)(smem + MOFF_OFF);

    // ---- epilogue ----
    #pragma unroll
    for (int mt = 0; mt < 2; mt++) {
        const int r0 = wm * 32 + mt * 16 + g;
        const float rb0 = -0.5f * g_e2[m0 + r0];
        const float rb1 = -0.5f * g_e2[m0 + r0 + 8];
        float* orow0 = out + (size_t)(m0 + r0) * GS_L;
        float* orow1 = orow0 + 8 * GS_L;
        #pragma unroll
        for (int nt = 0; nt < 4; nt++) {
            const int col = wn * 32 + nt * 8 + tig * 2;
            float2 mo = *(const float2*)(moff + col);
            float2 o0, o1;
            o0.x = acc[mt][nt][0] + rb0 + mo.x;
            o0.y = acc[mt][nt][1] + rb0 + mo.y;
            o1.x = acc[mt][nt][2] + rb1 + mo.x;
            o1.y = acc[mt][nt][3] + rb1 + mo.y;
            *(float2*)(orow0 + col) = o0;
            *(float2*)(orow1 + col) = o1;
        }
    }
}

extern "C" void kernel_launch(void* const* d_in, const int* in_sizes, int n_in,
                              void* d_out, int out_size) {
    const float* emb   = (const float*)d_in[0];   // [8, 2048, 512] f32
    const float* means = (const float*)d_in[1];   // [128, 512] f32
    const float* var   = (const float*)d_in[2];   // [512] f32
    float* out = (float*)d_out;                   // [8, 2048, 128] f32
    (void)in_sizes; (void)n_in; (void)out_size;

    cudaFuncSetAttribute(gs_mm, cudaFuncAttributeMaxDynamicSharedMemorySize, SMEM_MM);
    gs_convert<<<GS_M / 8 + 16, 256>>>(emb, means, var);
    gs_mm<<<GS_M / BM, 512, SMEM_MM>>>(out);
}